// round 9
// baseline (speedup 1.0000x reference)
#include <cuda_runtime.h>
#include <cuda_fp16.h>
#include <math.h>
#include <stdint.h>

#define N_NODES 100000
#define N_EDGES 1600000

// -------- scratch (static device allocation; no cudaMalloc anywhere) --------
__device__ float  g_xr[(size_t)N_NODES * 128];   // x rounded to tf32
__device__ __half g_t[(size_t)N_NODES * 128];    // X @ Wn  (fp16)
__device__ __half g_ts[(size_t)N_NODES * 128];   // X @ Ws  (fp16)
__device__ float  g_h1[(size_t)N_NODES * 256];   // layer-1 output (tf32-rounded)
__device__ float  g_h2[(size_t)N_NODES * 256];   // layer-2 output (tf32-rounded)
__device__ float  g_cnt[N_NODES];
__device__ int    g_deg[N_NODES];
__device__ int    g_cursor[N_NODES];
__device__ int    g_rowptr[N_NODES + 1];
__device__ int    g_adj[N_EDGES];
// W layout: per proj, per 64-col block, per kb(32-k tile): [g(8)][k(32)][j(8)] floats
__device__ float  g_wswz[(128 + 128 + 256 + 256) * 128];
__device__ float  g_wfcr[256 * 40];

#define W1N_OFF 0
#define W1S_OFF (128 * 128)
#define W2N_OFF (2 * 128 * 128)
#define W2S_OFF (2 * 128 * 128 + 256 * 128)

// ---------------------------------------------------------------------------
__device__ __forceinline__ float to_tf32(float x) {
    asm("cvt.rna.tf32.f32 %0, %1;" : "=f"(x) : "f"(x));
    return x;
}

// W [K][128] -> g-major tiled: off + blk*K*64 + kb*2048 + g*256 + kk*8 + j
template <int K>
__device__ __forceinline__ void swz_one(const float* __restrict__ w, int off, int i) {
    int k = i >> 7, n = i & 127;
    int blk = n >> 6, np = n & 63;
    int g = np & 7, j = np >> 3;
    int kb = k >> 5, kk = k & 31;
    g_wswz[off + blk * (K * 64) + kb * 2048 + g * 256 + kk * 8 + j] = to_tf32(w[i]);
}

__global__ void zero_dc_kernel() {
    int i = blockIdx.x * blockDim.x + threadIdx.x;
    if (i < N_NODES) { g_deg[i] = 0; g_cursor[i] = 0; }
}

__global__ void prep_kernel(const float* __restrict__ x,
                            const float* __restrict__ w1n, const float* __restrict__ w1s,
                            const float* __restrict__ w2n, const float* __restrict__ w2s,
                            const float* __restrict__ wfc) {
    int idx = blockIdx.x * blockDim.x + threadIdx.x;
    int stride = gridDim.x * blockDim.x;
    for (int i = idx; i < N_NODES * 32; i += stride) {
        float4 v = ((const float4*)x)[i];
        v.x = to_tf32(v.x); v.y = to_tf32(v.y); v.z = to_tf32(v.z); v.w = to_tf32(v.w);
        ((float4*)g_xr)[i] = v;
    }
    for (int i = idx; i < 128 * 128; i += stride) swz_one<128>(w1n, W1N_OFF, i);
    for (int i = idx; i < 128 * 128; i += stride) swz_one<128>(w1s, W1S_OFF, i);
    for (int i = idx; i < 256 * 128; i += stride) swz_one<256>(w2n, W2N_OFF, i);
    for (int i = idx; i < 256 * 128; i += stride) swz_one<256>(w2s, W2S_OFF, i);
    for (int i = idx; i < 256 * 40; i += stride) g_wfcr[i] = to_tf32(wfc[i]);
}

// ---------------------------------------------------------------------------
// CSR build
__global__ void count_kernel(const int* __restrict__ dst) {
    int e4 = blockIdx.x * blockDim.x + threadIdx.x;
    int base = e4 * 4;
    if (base + 4 <= N_EDGES) {
        int4 d = *(const int4*)&dst[base];
        atomicAdd(&g_deg[d.x], 1);
        atomicAdd(&g_deg[d.y], 1);
        atomicAdd(&g_deg[d.z], 1);
        atomicAdd(&g_deg[d.w], 1);
    } else {
        for (int e = base; e < N_EDGES; ++e) atomicAdd(&g_deg[dst[e]], 1);
    }
}

__global__ __launch_bounds__(1024)
void scan_kernel() {
    __shared__ int wsum[32];
    __shared__ int carry_s;
    int tid = threadIdx.x, lane = tid & 31, wid = tid >> 5;
    if (tid == 0) carry_s = 0;
    __syncthreads();
    for (int base = 0; base < N_NODES; base += 1024) {
        int carry = carry_s;
        int i = base + tid;
        int v = (i < N_NODES) ? g_deg[i] : 0;
        int x = v;
#pragma unroll
        for (int o = 1; o < 32; o <<= 1) {
            int y = __shfl_up_sync(0xffffffffu, x, o);
            if (lane >= o) x += y;
        }
        if (lane == 31) wsum[wid] = x;
        __syncthreads();
        if (wid == 0) {
            int s = wsum[lane];
#pragma unroll
            for (int o = 1; o < 32; o <<= 1) {
                int y = __shfl_up_sync(0xffffffffu, s, o);
                if (lane >= o) s += y;
            }
            wsum[lane] = s;
        }
        __syncthreads();
        int incl = x + (wid ? wsum[wid - 1] : 0) + carry;
        if (i < N_NODES) { g_rowptr[i] = incl - v; g_cnt[i] = (float)v; }
        __syncthreads();
        if (tid == 1023) carry_s = incl;
        __syncthreads();
    }
    if (threadIdx.x == 0) g_rowptr[N_NODES] = carry_s;
}

__global__ void fill_kernel(const int* __restrict__ src, const int* __restrict__ dst) {
    int e = blockIdx.x * blockDim.x + threadIdx.x;
    if (e < N_EDGES) {
        int d = dst[e];
        int pos = atomicAdd(&g_cursor[d], 1);
        g_adj[g_rowptr[d] + pos] = src[e];
    }
}

// ---------------------------------------------------------------------------
__device__ __forceinline__ float4 ld_t4(const __half* base, size_t off) {
    uint2 u = __ldg((const uint2*)(base + off));
    __half2 h0 = *reinterpret_cast<__half2*>(&u.x);
    __half2 h1 = *reinterpret_cast<__half2*>(&u.y);
    float2 f0 = __half22float2(h0);
    float2 f1 = __half22float2(h1);
    return make_float4(f0.x, f0.y, f1.x, f1.y);
}

// gather + full SAGE epilogue (one warp per node), unroll-8 on neighbors.
template <int LAYER>
__global__ __launch_bounds__(256)
void gather_epi_kernel(const float* __restrict__ bs, const float* __restrict__ bn) {
    int gw = (blockIdx.x * blockDim.x + threadIdx.x) >> 5;
    int lane = threadIdx.x & 31;
    if (gw >= N_NODES) return;
    int beg = g_rowptr[gw];
    int end = g_rowptr[gw + 1];
    const int c4 = lane * 4;

    float4 accA = make_float4(0.f, 0.f, 0.f, 0.f);
    float4 accB = make_float4(0.f, 0.f, 0.f, 0.f);
    for (int i = beg; i < end; i += 32) {
        int id = (i + lane < end) ? g_adj[i + lane] : 0;
        int m = min(32, end - i);
        int j = 0;
        for (; j + 8 <= m; j += 8) {          // 8 independent LDG.64 in flight
            float4 v[8];
#pragma unroll
            for (int q = 0; q < 8; ++q) {
                int s = __shfl_sync(0xffffffffu, id, j + q);
                v[q] = ld_t4(g_t, (size_t)s * 128 + c4);
            }
#pragma unroll
            for (int q = 0; q < 8; q += 2) {
                accA.x += v[q].x; accA.y += v[q].y; accA.z += v[q].z; accA.w += v[q].w;
                accB.x += v[q+1].x; accB.y += v[q+1].y; accB.z += v[q+1].z; accB.w += v[q+1].w;
            }
        }
        for (; j + 2 <= m; j += 2) {
            int s0 = __shfl_sync(0xffffffffu, id, j);
            int s1 = __shfl_sync(0xffffffffu, id, j + 1);
            float4 v0 = ld_t4(g_t, (size_t)s0 * 128 + c4);
            float4 v1 = ld_t4(g_t, (size_t)s1 * 128 + c4);
            accA.x += v0.x; accA.y += v0.y; accA.z += v0.z; accA.w += v0.w;
            accB.x += v1.x; accB.y += v1.y; accB.z += v1.z; accB.w += v1.w;
        }
        if (j < m) {
            int s0 = __shfl_sync(0xffffffffu, id, j);
            float4 v0 = ld_t4(g_t, (size_t)s0 * 128 + c4);
            accA.x += v0.x; accA.y += v0.y; accA.z += v0.z; accA.w += v0.w;
        }
    }
    float4 acc = make_float4(accA.x + accB.x, accA.y + accB.y,
                             accA.z + accB.z, accA.w + accB.w);

    float inv = 1.f / fmaxf(g_cnt[gw], 1.f);
    float4 ts  = ld_t4(g_ts, (size_t)gw * 128 + c4);
    float4 bsv = *(const float4*)&bs[c4];
    float4 bnv = *(const float4*)&bn[c4];

    float s0 = fmaxf(ts.x + bsv.x, 0.f), s1 = fmaxf(ts.y + bsv.y, 0.f);
    float s2 = fmaxf(ts.z + bsv.z, 0.f), s3 = fmaxf(ts.w + bsv.w, 0.f);
    float a0 = fmaxf(acc.x * inv + bnv.x, 0.f), a1 = fmaxf(acc.y * inv + bnv.y, 0.f);
    float a2 = fmaxf(acc.z * inv + bnv.z, 0.f), a3 = fmaxf(acc.w * inv + bnv.w, 0.f);

    float ss = s0 * s0 + s1 * s1 + s2 * s2 + s3 * s3
             + a0 * a0 + a1 * a1 + a2 * a2 + a3 * a3;
#pragma unroll
    for (int o = 16; o > 0; o >>= 1) ss += __shfl_xor_sync(0xffffffffu, ss, o);
    float sc = 1.f / fmaxf(sqrtf(ss), 1e-12f);

    s0 = to_tf32(s0 * sc); s1 = to_tf32(s1 * sc); s2 = to_tf32(s2 * sc); s3 = to_tf32(s3 * sc);
    a0 = to_tf32(a0 * sc); a1 = to_tf32(a1 * sc); a2 = to_tf32(a2 * sc); a3 = to_tf32(a3 * sc);
    float* H = (LAYER == 1) ? g_h1 : g_h2;
    *(float4*)&H[(size_t)gw * 256 + c4]       = make_float4(s0, s1, s2, s3);
    *(float4*)&H[(size_t)gw * 256 + 128 + c4] = make_float4(a0, a1, a2, a3);
}

// ---------------------------------------------------------------------------
__device__ __forceinline__ void mma_tf32(float c[4],
                                         uint32_t a0, uint32_t a1, uint32_t a2, uint32_t a3,
                                         uint32_t b0, uint32_t b1) {
    asm volatile(
        "mma.sync.aligned.m16n8k8.row.col.f32.tf32.tf32.f32 "
        "{%0,%1,%2,%3}, {%4,%5,%6,%7}, {%8,%9}, {%0,%1,%2,%3};"
        : "+f"(c[0]), "+f"(c[1]), "+f"(c[2]), "+f"(c[3])
        : "r"(a0), "r"(a1), "r"(a2), "r"(a3), "r"(b0), "r"(b1));
}

__device__ __forceinline__ void cp_cg(uint32_t d, const void* s) {
    asm volatile("cp.async.cg.shared.global [%0], [%1], 16;" :: "r"(d), "l"(s));
}
__device__ __forceinline__ void cp_commit() { asm volatile("cp.async.commit_group;"); }
template <int NW>
__device__ __forceinline__ void cp_wait() { asm volatile("cp.async.wait_group %0;" :: "n"(NW)); }

// GEMM (tf32 MMA, cp.async double-buffered), output tile 128 rows x 64 cols.
//   grid.y in 0..3: proj = y>>1 (0: Wn -> g_t, 1: Ws -> g_ts), blk = y&1 (col half)
//   warp = 16 rows x 64 cols (8 n-tiles, 32 acc regs). 3 blocks/SM target.
// W smem layout (per kb tile): [g(8)][k(32)][j(8)], g-stride 260 floats (bank-clean).
template <int K>
__global__ __launch_bounds__(256, 3)
void sage_gemm_tc(int woffN, int woffS) {
    constexpr int XS = 36;
    constexpr int XB = 128 * XS;     // floats per X buffer
    constexpr int WB = 8 * 260;      // 2080 floats per W buffer
    constexpr int NKB = K / 32;

    extern __shared__ float smem[];
    float* Xs = smem;                // 2 buffers
    float* Ws = smem + 2 * XB;       // 2 buffers

    const int tid = threadIdx.x;
    const int lane = tid & 31;
    const int w = tid >> 5;
    const int g = lane >> 2;
    const int t = lane & 3;
    const int rowBase = blockIdx.x * 128;
    const int proj = blockIdx.y >> 1;
    const int blk = blockIdx.y & 1;
    const float* X = (K == 256) ? (const float*)g_h1 : (const float*)g_xr;
    const float* Wg = g_wswz + (proj ? woffS : woffN) + blk * (K * 64);
    __half* dstbuf = proj ? g_ts : g_t;
    const int colBase = blk * 64;

    const uint32_t xs_base = (uint32_t)__cvta_generic_to_shared(Xs);
    const uint32_t ws_base = (uint32_t)__cvta_generic_to_shared(Ws);

    float c[8][4];
#pragma unroll
    for (int i = 0; i < 8; ++i) { c[i][0] = c[i][1] = c[i][2] = c[i][3] = 0.f; }

    auto stage = [&](int buf, int kb) {
        // X tile 128x32 (1024 uint4, 4/thread)
#pragma unroll
        for (int it = 0; it < 4; ++it) {
            int idx = tid + it * 256;
            int r = idx >> 3, cc = idx & 7;
            int grow = min(rowBase + r, N_NODES - 1);
            uint32_t d = xs_base + (uint32_t)buf * XB * 4 + r * 144 + cc * 16;
            cp_cg(d, &X[(size_t)grow * K + kb * 32 + cc * 4]);
        }
        // W tile: 512 uint4 chunks (2/thread): c -> (g = c>>6, k = (c&63)>>1, q = c&1)
#pragma unroll
        for (int it = 0; it < 2; ++it) {
            int cch = tid + it * 256;
            int gg = cch >> 6, rem = cch & 63;
            int kk = rem >> 1, q = rem & 1;
            uint32_t d = ws_base + ((uint32_t)buf * WB + gg * 260 + kk * 8 + q * 4) * 4;
            cp_cg(d, &Wg[(size_t)kb * 2048 + gg * 256 + kk * 8 + q * 4]);
        }
    };

    stage(0, 0);
    cp_commit();

#pragma unroll
    for (int kb = 0; kb < NKB; ++kb) {
        if (kb + 1 < NKB) {
            stage((kb + 1) & 1, kb + 1);
            cp_commit();
            cp_wait<1>();
        } else {
            cp_wait<0>();
        }
        __syncthreads();

        const uint32_t* Xu = (const uint32_t*)(Xs + (kb & 1) * XB);
        const uint32_t* Wu = (const uint32_t*)(Ws + (kb & 1) * WB);
#pragma unroll
        for (int ks = 0; ks < 4; ++ks) {
            const int kl = ks * 8;
            const int ar = w * 16 + g;
            uint32_t a0 = Xu[ar * XS + kl + t];
            uint32_t a1 = Xu[(ar + 8) * XS + kl + t];
            uint32_t a2 = Xu[ar * XS + kl + t + 4];
            uint32_t a3 = Xu[(ar + 8) * XS + kl + t + 4];
            uint4 blo[2], bhi[2];
#pragma unroll
            for (int q = 0; q < 2; ++q) {
                blo[q] = *(const uint4*)&Wu[g * 260 + (kl + t) * 8 + q * 4];
                bhi[q] = *(const uint4*)&Wu[g * 260 + (kl + t + 4) * 8 + q * 4];
            }
#pragma unroll
            for (int nt = 0; nt < 8; ++nt) {
                uint32_t b0 = ((const uint32_t*)&blo[nt >> 2])[nt & 3];
                uint32_t b1 = ((const uint32_t*)&bhi[nt >> 2])[nt & 3];
                mma_tf32(c[nt], a0, a1, a2, a3, b0, b1);
            }
        }
        __syncthreads();
    }

    const int r1 = rowBase + w * 16 + g;
    const int r2 = r1 + 8;
    const bool v1 = r1 < N_NODES;
    const bool v2 = r2 < N_NODES;
#pragma unroll
    for (int nt = 0; nt < 8; ++nt) {
        int col = colBase + nt * 8 + 2 * t;
        if (v1) *(__half2*)&dstbuf[(size_t)r1 * 128 + col] =
            __float22half2_rn(make_float2(c[nt][0], c[nt][1]));
        if (v2) *(__half2*)&dstbuf[(size_t)r2 * 128 + col] =
            __float22half2_rn(make_float2(c[nt][2], c[nt][3]));
    }
}

// ---------------------------------------------------------------------------
// head (tf32 MMA): out[N,40] = h2[N,256] @ wfcr[256,40] + bfc
__global__ __launch_bounds__(256)
void head_tc(const float* __restrict__ bfc, float* __restrict__ out) {
    constexpr int XS = 36;
    constexpr int XB = 128 * XS;
    constexpr int WSTR = 44;

    extern __shared__ float smem[];
    float* Xs = smem;
    float* Wsm = smem + 2 * XB;

    const int tid = threadIdx.x;
    const int lane = tid & 31;
    const int w = tid >> 5;
    const int g = lane >> 2;
    const int t = lane & 3;
    const int rowBase = blockIdx.x * 128;

    const uint32_t xs_base = (uint32_t)__cvta_generic_to_shared(Xs);

    auto stageX = [&](int buf, int kb) {
#pragma unroll
        for (int it = 0; it < 4; ++it) {
            int idx = tid + it * 256;
            int r = idx >> 3, cc = idx & 7;
            int grow = min(rowBase + r, N_NODES - 1);
            uint32_t d = xs_base + (uint32_t)buf * XB * 4 + r * 144 + cc * 16;
            cp_cg(d, &g_h2[(size_t)grow * 256 + kb * 32 + cc * 4]);
        }
    };

    stageX(0, 0);
    cp_commit();

    for (int i = tid; i < 256 * 40; i += 256) {
        int k = i / 40, n = i % 40;
        Wsm[k * WSTR + n] = g_wfcr[i];
    }

    float c[5][4];
#pragma unroll
    for (int i = 0; i < 5; ++i) { c[i][0] = c[i][1] = c[i][2] = c[i][3] = 0.f; }

#pragma unroll
    for (int kb = 0; kb < 8; ++kb) {
        if (kb + 1 < 8) {
            stageX((kb + 1) & 1, kb + 1);
            cp_commit();
            cp_wait<1>();
        } else {
            cp_wait<0>();
        }
        __syncthreads();

        const uint32_t* Xu = (const uint32_t*)(Xs + (kb & 1) * XB);
#pragma unroll
        for (int ks = 0; ks < 4; ++ks) {
            const int kl = ks * 8;
            const int ar = w * 16 + g;
            uint32_t a0 = Xu[ar * XS + kl + t];
            uint32_t a1 = Xu[(ar + 8) * XS + kl + t];
            uint32_t a2 = Xu[ar * XS + kl + t + 4];
            uint32_t a3 = Xu[(ar + 8) * XS + kl + t + 4];
            const int krow = kb * 32 + kl;
#pragma unroll
            for (int nt = 0; nt < 5; ++nt) {
                uint32_t b0 = __float_as_uint(Wsm[(krow + t) * WSTR + nt * 8 + g]);
                uint32_t b1 = __float_as_uint(Wsm[(krow + t + 4) * WSTR + nt * 8 + g]);
                mma_tf32(c[nt], a0, a1, a2, a3, b0, b1);
            }
        }
        __syncthreads();
    }

    const int r1 = rowBase + w * 16 + g;
    const int r2 = r1 + 8;
#pragma unroll
    for (int nt = 0; nt < 5; ++nt) {
        int col = nt * 8 + 2 * t;
        float2 b = *(const float2*)&bfc[col];
        if (r1 < N_NODES) *(float2*)&out[(size_t)r1 * 40 + col] = make_float2(c[nt][0] + b.x, c[nt][1] + b.y);
        if (r2 < N_NODES) *(float2*)&out[(size_t)r2 * 40 + col] = make_float2(c[nt][2] + b.x, c[nt][3] + b.y);
    }
}

// ---------------------------------------------------------------------------
extern "C" void kernel_launch(void* const* d_in, const int* in_sizes, int n_in,
                              void* d_out, int out_size) {
    const float* x   = (const float*)d_in[0];
    const int*   src = (const int*)d_in[1];
    const int*   dst = (const int*)d_in[2];
    const float* w1s = (const float*)d_in[3];
    const float* b1s = (const float*)d_in[4];
    const float* w1n = (const float*)d_in[5];
    const float* b1n = (const float*)d_in[6];
    const float* w2s = (const float*)d_in[7];
    const float* b2s = (const float*)d_in[8];
    const float* w2n = (const float*)d_in[9];
    const float* b2n = (const float*)d_in[10];
    const float* wfc = (const float*)d_in[11];
    const float* bfc = (const float*)d_in[12];
    float* out = (float*)d_out;

    const int SMEM_GEMM = (2 * 128 * 36 + 2 * 8 * 260) * 4;      // 53504
    const int SMEM_HEAD = (2 * 128 * 36 + 256 * 44) * 4;         // 81920
    static int attr_done = 0;
    if (!attr_done) {
        cudaFuncSetAttribute(sage_gemm_tc<128>, cudaFuncAttributeMaxDynamicSharedMemorySize, SMEM_GEMM);
        cudaFuncSetAttribute(sage_gemm_tc<256>, cudaFuncAttributeMaxDynamicSharedMemorySize, SMEM_GEMM);
        cudaFuncSetAttribute(head_tc, cudaFuncAttributeMaxDynamicSharedMemorySize, SMEM_HEAD);
        attr_done = 1;
    }

    const dim3 gemm_grid((N_NODES + 127) / 128, 4);  // y = proj*2 + col-half
    const int gath_blocks = (N_NODES + 7) / 8;
    const int edge_blocks = (N_EDGES + 255) / 256;
    const int head_blocks = (N_NODES + 127) / 128;

    // order keeps sage_gemm_tc<128> in the ncu capture slot (launch #4)
    zero_dc_kernel<<<(N_NODES + 255) / 256, 256>>>();                      // 1
    count_kernel<<<(N_EDGES / 4 + 255) / 256, 256>>>(dst);                 // 2
    prep_kernel<<<2048, 256>>>(x, w1n, w1s, w2n, w2s, wfc);                // 3
    sage_gemm_tc<128><<<gemm_grid, 256, SMEM_GEMM>>>(W1N_OFF, W1S_OFF);    // 4  <- profiled
    scan_kernel<<<1, 1024>>>();                                            // 5
    fill_kernel<<<edge_blocks, 256>>>(src, dst);                           // 6
    gather_epi_kernel<1><<<gath_blocks, 256>>>(b1s, b1n);                  // 7
    sage_gemm_tc<256><<<gemm_grid, 256, SMEM_GEMM>>>(W2N_OFF, W2S_OFF);    // 8
    gather_epi_kernel<2><<<gath_blocks, 256>>>(b2s, b2n);                  // 9
    head_tc<<<head_blocks, 256, SMEM_HEAD>>>(bfc, out);                    // 10
}

// round 10
// speedup vs baseline: 1.3317x; 1.3317x over previous
#include <cuda_runtime.h>
#include <cuda_fp16.h>
#include <math.h>
#include <stdint.h>

#define N_NODES 100000
#define N_EDGES 1600000

// -------- scratch (static device allocation; no cudaMalloc anywhere) --------
__device__ __half g_xh[(size_t)N_NODES * 128];   // x rounded to fp16
__device__ __half g_t[(size_t)N_NODES * 128];    // X @ Wn  (fp16)
__device__ __half g_ts[(size_t)N_NODES * 128];   // X @ Ws  (fp16)
__device__ __half g_h1h[(size_t)N_NODES * 256];  // layer-1 output (fp16)
__device__ float  g_h2[(size_t)N_NODES * 256];   // layer-2 output (tf32-rounded fp32)
__device__ float  g_cnt[N_NODES];
__device__ int    g_deg[N_NODES];
__device__ int    g_cursor[N_NODES];
__device__ int    g_rowptr[N_NODES + 1];
__device__ int    g_adj[N_EDGES];
// packed fp16 weights in B-fragment order:
//   per proj: [s = k/16][tt = (k%16)/2][nsw = (n&7)*16 + (n>>3)] -> u32 = half2(W[k][n], W[k+1][n])
__device__ uint32_t g_wp[(128 + 128 + 256 + 256) * 128 / 2];
__device__ float  g_wfcr[256 * 40];              // wfc rounded to tf32 (head)

#define W1N_OFF 0
#define W1S_OFF 8192
#define W2N_OFF 16384
#define W2S_OFF 32768

// ---------------------------------------------------------------------------
__device__ __forceinline__ float to_tf32(float x) {
    asm("cvt.rna.tf32.f32 %0, %1;" : "=f"(x) : "f"(x));
    return x;
}

__global__ void zero_dc_kernel() {
    int i = blockIdx.x * blockDim.x + threadIdx.x;
    if (i < N_NODES) { g_deg[i] = 0; g_cursor[i] = 0; }
}

// pack one weight matrix [K][128] into fragment order (see g_wp comment)
template <int K>
__device__ __forceinline__ void pack_one(const float* __restrict__ w, int off, int i) {
    int k2 = i >> 7, n = i & 127;
    int k = 2 * k2;
    int s = k >> 4, tt = (k & 15) >> 1;
    __half2 v = __floats2half2_rn(w[k * 128 + n], w[(k + 1) * 128 + n]);
    g_wp[off + s * 1024 + tt * 128 + (n & 7) * 16 + (n >> 3)] = *(uint32_t*)&v;
}

__global__ void prep_kernel(const float* __restrict__ x,
                            const float* __restrict__ w1n, const float* __restrict__ w1s,
                            const float* __restrict__ w2n, const float* __restrict__ w2s,
                            const float* __restrict__ wfc) {
    int idx = blockIdx.x * blockDim.x + threadIdx.x;
    int stride = gridDim.x * blockDim.x;
    __half2* xh2 = (__half2*)g_xh;
    for (int i = idx; i < N_NODES * 64; i += stride) {
        float2 v = ((const float2*)x)[i];
        xh2[i] = __floats2half2_rn(v.x, v.y);
    }
    for (int i = idx; i < 64 * 128; i += stride) pack_one<128>(w1n, W1N_OFF, i);
    for (int i = idx; i < 64 * 128; i += stride) pack_one<128>(w1s, W1S_OFF, i);
    for (int i = idx; i < 128 * 128; i += stride) pack_one<256>(w2n, W2N_OFF, i);
    for (int i = idx; i < 128 * 128; i += stride) pack_one<256>(w2s, W2S_OFF, i);
    for (int i = idx; i < 256 * 40; i += stride) g_wfcr[i] = to_tf32(wfc[i]);
}

// ---------------------------------------------------------------------------
// CSR build
__global__ void count_kernel(const int* __restrict__ dst) {
    int e4 = blockIdx.x * blockDim.x + threadIdx.x;
    int base = e4 * 4;
    if (base + 4 <= N_EDGES) {
        int4 d = *(const int4*)&dst[base];
        atomicAdd(&g_deg[d.x], 1);
        atomicAdd(&g_deg[d.y], 1);
        atomicAdd(&g_deg[d.z], 1);
        atomicAdd(&g_deg[d.w], 1);
    } else {
        for (int e = base; e < N_EDGES; ++e) atomicAdd(&g_deg[dst[e]], 1);
    }
}

__global__ __launch_bounds__(1024)
void scan_kernel() {
    __shared__ int wsum[32];
    __shared__ int carry_s;
    int tid = threadIdx.x, lane = tid & 31, wid = tid >> 5;
    if (tid == 0) carry_s = 0;
    __syncthreads();
    for (int base = 0; base < N_NODES; base += 1024) {
        int carry = carry_s;
        int i = base + tid;
        int v = (i < N_NODES) ? g_deg[i] : 0;
        int x = v;
#pragma unroll
        for (int o = 1; o < 32; o <<= 1) {
            int y = __shfl_up_sync(0xffffffffu, x, o);
            if (lane >= o) x += y;
        }
        if (lane == 31) wsum[wid] = x;
        __syncthreads();
        if (wid == 0) {
            int s = wsum[lane];
#pragma unroll
            for (int o = 1; o < 32; o <<= 1) {
                int y = __shfl_up_sync(0xffffffffu, s, o);
                if (lane >= o) s += y;
            }
            wsum[lane] = s;
        }
        __syncthreads();
        int incl = x + (wid ? wsum[wid - 1] : 0) + carry;
        if (i < N_NODES) { g_rowptr[i] = incl - v; g_cnt[i] = (float)v; }
        __syncthreads();
        if (tid == 1023) carry_s = incl;
        __syncthreads();
    }
    if (threadIdx.x == 0) g_rowptr[N_NODES] = carry_s;
}

__global__ void fill_kernel(const int* __restrict__ src, const int* __restrict__ dst) {
    int e = blockIdx.x * blockDim.x + threadIdx.x;
    if (e < N_EDGES) {
        int d = dst[e];
        int pos = atomicAdd(&g_cursor[d], 1);
        g_adj[g_rowptr[d] + pos] = src[e];
    }
}

// ---------------------------------------------------------------------------
__device__ __forceinline__ float4 ld_t4(const __half* base, size_t off) {
    uint2 u = __ldg((const uint2*)(base + off));
    __half2 h0 = *reinterpret_cast<__half2*>(&u.x);
    __half2 h1 = *reinterpret_cast<__half2*>(&u.y);
    float2 f0 = __half22float2(h0);
    float2 f1 = __half22float2(h1);
    return make_float4(f0.x, f0.y, f1.x, f1.y);
}

// gather + full SAGE epilogue (one warp per node), unroll-4 (R8-proven).
// LAYER==1: writes fp16 h1 (feeds fp16 MMA); LAYER==2: writes tf32-rounded fp32 h2.
template <int LAYER>
__global__ __launch_bounds__(256)
void gather_epi_kernel(const float* __restrict__ bs, const float* __restrict__ bn) {
    int gw = (blockIdx.x * blockDim.x + threadIdx.x) >> 5;
    int lane = threadIdx.x & 31;
    if (gw >= N_NODES) return;
    int beg = g_rowptr[gw];
    int end = g_rowptr[gw + 1];
    const int c4 = lane * 4;

    float4 accA = make_float4(0.f, 0.f, 0.f, 0.f);
    float4 accB = make_float4(0.f, 0.f, 0.f, 0.f);
    for (int i = beg; i < end; i += 32) {
        int id = (i + lane < end) ? g_adj[i + lane] : 0;
        int m = min(32, end - i);
        int j = 0;
        for (; j + 4 <= m; j += 4) {
            int s0 = __shfl_sync(0xffffffffu, id, j);
            int s1 = __shfl_sync(0xffffffffu, id, j + 1);
            int s2 = __shfl_sync(0xffffffffu, id, j + 2);
            int s3 = __shfl_sync(0xffffffffu, id, j + 3);
            float4 v0 = ld_t4(g_t, (size_t)s0 * 128 + c4);
            float4 v1 = ld_t4(g_t, (size_t)s1 * 128 + c4);
            float4 v2 = ld_t4(g_t, (size_t)s2 * 128 + c4);
            float4 v3 = ld_t4(g_t, (size_t)s3 * 128 + c4);
            accA.x += v0.x + v1.x; accA.y += v0.y + v1.y;
            accA.z += v0.z + v1.z; accA.w += v0.w + v1.w;
            accB.x += v2.x + v3.x; accB.y += v2.y + v3.y;
            accB.z += v2.z + v3.z; accB.w += v2.w + v3.w;
        }
        for (; j < m; ++j) {
            int s0 = __shfl_sync(0xffffffffu, id, j);
            float4 v0 = ld_t4(g_t, (size_t)s0 * 128 + c4);
            accA.x += v0.x; accA.y += v0.y; accA.z += v0.z; accA.w += v0.w;
        }
    }
    float4 acc = make_float4(accA.x + accB.x, accA.y + accB.y,
                             accA.z + accB.z, accA.w + accB.w);

    float inv = 1.f / fmaxf(g_cnt[gw], 1.f);
    float4 ts  = ld_t4(g_ts, (size_t)gw * 128 + c4);
    float4 bsv = *(const float4*)&bs[c4];
    float4 bnv = *(const float4*)&bn[c4];

    float s0 = fmaxf(ts.x + bsv.x, 0.f), s1 = fmaxf(ts.y + bsv.y, 0.f);
    float s2 = fmaxf(ts.z + bsv.z, 0.f), s3 = fmaxf(ts.w + bsv.w, 0.f);
    float a0 = fmaxf(acc.x * inv + bnv.x, 0.f), a1 = fmaxf(acc.y * inv + bnv.y, 0.f);
    float a2 = fmaxf(acc.z * inv + bnv.z, 0.f), a3 = fmaxf(acc.w * inv + bnv.w, 0.f);

    float ss = s0 * s0 + s1 * s1 + s2 * s2 + s3 * s3
             + a0 * a0 + a1 * a1 + a2 * a2 + a3 * a3;
#pragma unroll
    for (int o = 16; o > 0; o >>= 1) ss += __shfl_xor_sync(0xffffffffu, ss, o);
    float sc = 1.f / fmaxf(sqrtf(ss), 1e-12f);

    s0 *= sc; s1 *= sc; s2 *= sc; s3 *= sc;
    a0 *= sc; a1 *= sc; a2 *= sc; a3 *= sc;

    if (LAYER == 1) {
        __half2* H2 = (__half2*)&g_h1h[(size_t)gw * 256 + c4];
        H2[0] = __floats2half2_rn(s0, s1);
        H2[1] = __floats2half2_rn(s2, s3);
        __half2* H2n = (__half2*)&g_h1h[(size_t)gw * 256 + 128 + c4];
        H2n[0] = __floats2half2_rn(a0, a1);
        H2n[1] = __floats2half2_rn(a2, a3);
    } else {
        s0 = to_tf32(s0); s1 = to_tf32(s1); s2 = to_tf32(s2); s3 = to_tf32(s3);
        a0 = to_tf32(a0); a1 = to_tf32(a1); a2 = to_tf32(a2); a3 = to_tf32(a3);
        *(float4*)&g_h2[(size_t)gw * 256 + c4]       = make_float4(s0, s1, s2, s3);
        *(float4*)&g_h2[(size_t)gw * 256 + 128 + c4] = make_float4(a0, a1, a2, a3);
    }
}

// ---------------------------------------------------------------------------
__device__ __forceinline__ void mma_f16(float c[4],
                                        uint32_t a0, uint32_t a1, uint32_t a2, uint32_t a3,
                                        uint32_t b0, uint32_t b1) {
    asm volatile(
        "mma.sync.aligned.m16n8k16.row.col.f32.f16.f16.f32 "
        "{%0,%1,%2,%3}, {%4,%5,%6,%7}, {%8,%9}, {%0,%1,%2,%3};"
        : "+f"(c[0]), "+f"(c[1]), "+f"(c[2]), "+f"(c[3])
        : "r"(a0), "r"(a1), "r"(a2), "r"(a3), "r"(b0), "r"(b1));
}

__device__ __forceinline__ void mma_tf32(float c[4],
                                         uint32_t a0, uint32_t a1, uint32_t a2, uint32_t a3,
                                         uint32_t b0, uint32_t b1) {
    asm volatile(
        "mma.sync.aligned.m16n8k8.row.col.f32.tf32.tf32.f32 "
        "{%0,%1,%2,%3}, {%4,%5,%6,%7}, {%8,%9}, {%0,%1,%2,%3};"
        : "+f"(c[0]), "+f"(c[1]), "+f"(c[2]), "+f"(c[3])
        : "r"(a0), "r"(a1), "r"(a2), "r"(a3), "r"(b0), "r"(b1));
}

__device__ __forceinline__ void ldmatrix_x4(uint32_t& r0, uint32_t& r1,
                                            uint32_t& r2, uint32_t& r3, uint32_t addr) {
    asm volatile("ldmatrix.sync.aligned.m8n8.x4.shared.b16 {%0,%1,%2,%3}, [%4];"
                 : "=r"(r0), "=r"(r1), "=r"(r2), "=r"(r3) : "r"(addr));
}

__device__ __forceinline__ void cp_cg(uint32_t d, const void* s) {
    asm volatile("cp.async.cg.shared.global [%0], [%1], 16;" :: "r"(d), "l"(s));
}
__device__ __forceinline__ void cp_commit() { asm volatile("cp.async.commit_group;"); }
template <int NW>
__device__ __forceinline__ void cp_wait() { asm volatile("cp.async.wait_group %0;" :: "n"(NW)); }

// GEMM (fp16 MMA m16n8k16, cp.async double-buffered): both projections per layer.
//   grid.y: 0 -> X @ Wn -> g_t ; 1 -> X @ Ws -> g_ts
// Block 128 rows x 128 cols, 8 warps; warp = 16 rows x 128 cols.
// X smem: fp16, row stride 80 B (ldmatrix bank-clean). W smem: u32 frag pairs,
// [s(2)][tt(8) stride 132 u32][nsw(128)] (LDS.128 phases bank-clean).
template <int K>
__global__ __launch_bounds__(256)
void sage_gemm_tc(int woffN, int woffS) {
    constexpr int XROWB = 80;                 // bytes per X smem row
    constexpr int XBb = 128 * XROWB;          // 10240 B per X buffer
    constexpr int WB = 2 * 1056;              // u32 per W buffer (2 s-steps, tt-stride 132)
    constexpr int NKB = K / 32;

    extern __shared__ __align__(16) char smem[];
    char* Xs = smem;                              // 2 * XBb bytes
    uint32_t* Ws = (uint32_t*)(smem + 2 * XBb);   // 2 * WB u32

    const int tid = threadIdx.x;
    const int lane = tid & 31;
    const int w = tid >> 5;
    const int g = lane >> 2;
    const int t = lane & 3;
    const int rowBase = blockIdx.x * 128;
    const int proj = blockIdx.y;
    const __half* X = (K == 256) ? g_h1h : g_xh;
    const uint32_t* Wg = g_wp + (proj ? woffS : woffN);
    __half* dstbuf = proj ? g_ts : g_t;

    const uint32_t xs_base = (uint32_t)__cvta_generic_to_shared(Xs);
    const uint32_t ws_base = (uint32_t)__cvta_generic_to_shared(Ws);

    float c[16][4];
#pragma unroll
    for (int i = 0; i < 16; ++i) { c[i][0] = c[i][1] = c[i][2] = c[i][3] = 0.f; }

    // stage(buf, kb): X tile 128x32 halves (512 chunks) + W tile (512 chunks)
    auto stage = [&](int buf, int kb) {
#pragma unroll
        for (int it = 0; it < 2; ++it) {
            int ch = tid + it * 256;              // 0..511 -> X
            int r = ch >> 2, cc = ch & 3;
            int grow = min(rowBase + r, N_NODES - 1);
            uint32_t d = xs_base + (uint32_t)buf * XBb + r * XROWB + cc * 16;
            cp_cg(d, &X[(size_t)grow * K + kb * 32 + cc * 8]);
        }
#pragma unroll
        for (int it = 0; it < 2; ++it) {
            int ch = tid + it * 256;              // 0..511 -> W
            int s = ch >> 8, rem = ch & 255;
            int tt = rem >> 5, q = rem & 31;
            uint32_t d = ws_base + ((uint32_t)buf * WB + s * 1056 + tt * 132 + q * 4) * 4;
            cp_cg(d, &Wg[(size_t)(kb * 2 + s) * 1024 + tt * 128 + q * 4]);
        }
    };

    stage(0, 0);
    cp_commit();

    // ldmatrix per-lane address pieces (within an s-step)
    const int ltile = lane >> 3;                  // 0..3
    const int lrow = w * 16 + (ltile & 1) * 8 + (lane & 7);
    const uint32_t lkoff = (ltile >> 1) * 16;     // +16B for k8-15 tiles

#pragma unroll
    for (int kb = 0; kb < NKB; ++kb) {
        if (kb + 1 < NKB) {
            stage((kb + 1) & 1, kb + 1);
            cp_commit();
            cp_wait<1>();
        } else {
            cp_wait<0>();
        }
        __syncthreads();

        const uint32_t xbuf = xs_base + (uint32_t)(kb & 1) * XBb;
        const uint32_t* Wu = Ws + (kb & 1) * WB;
#pragma unroll
        for (int s = 0; s < 2; ++s) {
            uint32_t a0, a1, a2, a3;
            ldmatrix_x4(a0, a1, a2, a3, xbuf + lrow * XROWB + s * 32 + lkoff);
            uint4 blo[4], bhi[4];
#pragma unroll
            for (int q = 0; q < 4; ++q) {
                blo[q] = *(const uint4*)&Wu[s * 1056 + t * 132 + g * 16 + q * 4];
                bhi[q] = *(const uint4*)&Wu[s * 1056 + (t + 4) * 132 + g * 16 + q * 4];
            }
#pragma unroll
            for (int nt = 0; nt < 16; ++nt) {
                uint32_t b0 = ((const uint32_t*)&blo[nt >> 2])[nt & 3];
                uint32_t b1 = ((const uint32_t*)&bhi[nt >> 2])[nt & 3];
                mma_f16(c[nt], a0, a1, a2, a3, b0, b1);
            }
        }
        __syncthreads();
    }

    const int r1 = rowBase + w * 16 + g;
    const int r2 = r1 + 8;
    const bool v1 = r1 < N_NODES;
    const bool v2 = r2 < N_NODES;
#pragma unroll
    for (int nt = 0; nt < 16; ++nt) {
        int col = nt * 8 + 2 * t;
        if (v1) *(__half2*)&dstbuf[(size_t)r1 * 128 + col] =
            __floats2half2_rn(c[nt][0], c[nt][1]);
        if (v2) *(__half2*)&dstbuf[(size_t)r2 * 128 + col] =
            __floats2half2_rn(c[nt][2], c[nt][3]);
    }
}

// ---------------------------------------------------------------------------
// head (tf32 MMA): out[N,40] = h2[N,256] @ wfcr[256,40] + bfc   (unchanged, works)
__global__ __launch_bounds__(256)
void head_tc(const float* __restrict__ bfc, float* __restrict__ out) {
    constexpr int XS = 36;
    constexpr int XB = 128 * XS;
    constexpr int WSTR = 44;

    extern __shared__ __align__(16) char smemc[];
    float* Xs = (float*)smemc;
    float* Wsm = (float*)smemc + 2 * XB;

    const int tid = threadIdx.x;
    const int lane = tid & 31;
    const int w = tid >> 5;
    const int g = lane >> 2;
    const int t = lane & 3;
    const int rowBase = blockIdx.x * 128;

    const uint32_t xs_base = (uint32_t)__cvta_generic_to_shared(Xs);

    auto stageX = [&](int buf, int kb) {
#pragma unroll
        for (int it = 0; it < 4; ++it) {
            int idx = tid + it * 256;
            int r = idx >> 3, cc = idx & 7;
            int grow = min(rowBase + r, N_NODES - 1);
            uint32_t d = xs_base + (uint32_t)buf * XB * 4 + r * 144 + cc * 16;
            cp_cg(d, &g_h2[(size_t)grow * 256 + kb * 32 + cc * 4]);
        }
    };

    stageX(0, 0);
    cp_commit();

    for (int i = tid; i < 256 * 40; i += 256) {
        int k = i / 40, n = i % 40;
        Wsm[k * WSTR + n] = g_wfcr[i];
    }

    float c[5][4];
#pragma unroll
    for (int i = 0; i < 5; ++i) { c[i][0] = c[i][1] = c[i][2] = c[i][3] = 0.f; }

#pragma unroll
    for (int kb = 0; kb < 8; ++kb) {
        if (kb + 1 < 8) {
            stageX((kb + 1) & 1, kb + 1);
            cp_commit();
            cp_wait<1>();
        } else {
            cp_wait<0>();
        }
        __syncthreads();

        const uint32_t* Xu = (const uint32_t*)(Xs + (kb & 1) * XB);
#pragma unroll
        for (int ks = 0; ks < 4; ++ks) {
            const int kl = ks * 8;
            const int ar = w * 16 + g;
            uint32_t a0 = Xu[ar * XS + kl + t];
            uint32_t a1 = Xu[(ar + 8) * XS + kl + t];
            uint32_t a2 = Xu[ar * XS + kl + t + 4];
            uint32_t a3 = Xu[(ar + 8) * XS + kl + t + 4];
            const int krow = kb * 32 + kl;
#pragma unroll
            for (int nt = 0; nt < 5; ++nt) {
                uint32_t b0 = __float_as_uint(Wsm[(krow + t) * WSTR + nt * 8 + g]);
                uint32_t b1 = __float_as_uint(Wsm[(krow + t + 4) * WSTR + nt * 8 + g]);
                mma_tf32(c[nt], a0, a1, a2, a3, b0, b1);
            }
        }
        __syncthreads();
    }

    const int r1 = rowBase + w * 16 + g;
    const int r2 = r1 + 8;
#pragma unroll
    for (int nt = 0; nt < 5; ++nt) {
        int col = nt * 8 + 2 * t;
        float2 b = *(const float2*)&bfc[col];
        if (r1 < N_NODES) *(float2*)&out[(size_t)r1 * 40 + col] = make_float2(c[nt][0] + b.x, c[nt][1] + b.y);
        if (r2 < N_NODES) *(float2*)&out[(size_t)r2 * 40 + col] = make_float2(c[nt][2] + b.x, c[nt][3] + b.y);
    }
}

// ---------------------------------------------------------------------------
extern "C" void kernel_launch(void* const* d_in, const int* in_sizes, int n_in,
                              void* d_out, int out_size) {
    const float* x   = (const float*)d_in[0];
    const int*   src = (const int*)d_in[1];
    const int*   dst = (const int*)d_in[2];
    const float* w1s = (const float*)d_in[3];
    const float* b1s = (const float*)d_in[4];
    const float* w1n = (const float*)d_in[5];
    const float* b1n = (const float*)d_in[6];
    const float* w2s = (const float*)d_in[7];
    const float* b2s = (const float*)d_in[8];
    const float* w2n = (const float*)d_in[9];
    const float* b2n = (const float*)d_in[10];
    const float* wfc = (const float*)d_in[11];
    const float* bfc = (const float*)d_in[12];
    float* out = (float*)d_out;

    const int SMEM_GEMM = 2 * (128 * 80) + 2 * (2 * 1056) * 4;   // 20480 + 16896 = 37376
    const int SMEM_HEAD = (2 * 128 * 36 + 256 * 44) * 4;         // 81920
    static int attr_done = 0;
    if (!attr_done) {
        cudaFuncSetAttribute(sage_gemm_tc<128>, cudaFuncAttributeMaxDynamicSharedMemorySize, SMEM_GEMM);
        cudaFuncSetAttribute(sage_gemm_tc<256>, cudaFuncAttributeMaxDynamicSharedMemorySize, SMEM_GEMM);
        cudaFuncSetAttribute(head_tc, cudaFuncAttributeMaxDynamicSharedMemorySize, SMEM_HEAD);
        attr_done = 1;
    }

    const dim3 gemm_grid((N_NODES + 127) / 128, 2);  // y = proj
    const int gath_blocks = (N_NODES + 7) / 8;
    const int edge_blocks = (N_EDGES + 255) / 256;
    const int head_blocks = (N_NODES + 127) / 128;

    // order keeps sage_gemm_tc<128> in the ncu capture slot (launch #4)
    zero_dc_kernel<<<(N_NODES + 255) / 256, 256>>>();                      // 1
    count_kernel<<<(N_EDGES / 4 + 255) / 256, 256>>>(dst);                 // 2
    prep_kernel<<<2048, 256>>>(x, w1n, w1s, w2n, w2s, wfc);                // 3
    sage_gemm_tc<128><<<gemm_grid, 256, SMEM_GEMM>>>(W1N_OFF, W1S_OFF);    // 4  <- profiled
    scan_kernel<<<1, 1024>>>();                                            // 5
    fill_kernel<<<edge_blocks, 256>>>(src, dst);                           // 6
    gather_epi_kernel<1><<<gath_blocks, 256>>>(b1s, b1n);                  // 7
    sage_gemm_tc<256><<<gemm_grid, 256, SMEM_GEMM>>>(W2N_OFF, W2S_OFF);    // 8
    gather_epi_kernel<2><<<gath_blocks, 256>>>(b2s, b2n);                  // 9
    head_tc<<<head_blocks, 256, SMEM_HEAD>>>(bfc, out);                    // 10
}